// round 14
// baseline (speedup 1.0000x reference)
#include <cuda_runtime.h>
#include <cuda_fp16.h>
#include <cuda_bf16.h>
#include <math.h>
#include <stdint.h>

// prep-built weight images, LDG/cp.async-friendly order:
// u32 idx = ((kb*16 + warp)*32 + lane)*8 + nbi*2 + reg   (nbi = nb within warp)
__device__ __align__(16) uint32_t gWahHi[131072];
__device__ __align__(16) uint32_t gWahLo[131072];
__device__ __align__(16) uint32_t gWaaHi[131072];
__device__ __align__(16) uint32_t gWaaLo[131072];
__device__ __align__(16) uint32_t gWbHi [16384];
__device__ __align__(16) uint32_t gWbLo [16384];

namespace {
constexpr int H = 16, C = 32, HID = 512, SKUD = 64, ROWS = 32, NTHR = 512;
constexpr float TEMP_INV = 1.0f / 0.7f, TMAX = 365.0f, LN_EPS = 1e-3f;
constexpr int XSTR = 1040;                 // X image row stride in bytes (520 bf16)
// B prefetch ring: 3 stages, per-warp-per-lane 80B slot (64B used, pad kills conflicts)
constexpr int LSLOT  = 80;
constexpr int STAGEB = 16 * 32 * LSLOT;    // 40960 B per stage
// smem byte offsets
constexpr int OFF_XHI = 0;                 // 32*1040 = 33280
constexpr int OFF_XLO = 33280;
constexpr int OFF_BQ  = 66560;             // 3*40960 = 122880
constexpr int OFF_WO  = 189440;            // 512 f32
constexpr int OFF_PS0 = 191488;            // 16*32 f32
constexpr int OFF_PS1 = 193536;            // 16*32 f32
constexpr int OFF_GMX = 195584;            // 32 f32
constexpr int OFF_WAWO= 195712;            // 64 f32
constexpr int SMEM_BYTES = 195968;
}

using ull = unsigned long long;

__device__ __forceinline__ ull pack2(float x, float y) {
    ull r; asm("mov.b64 %0, {%1, %2};" : "=l"(r) : "f"(x), "f"(y)); return r;
}
__device__ __forceinline__ float2 unpack2(ull v) {
    float2 f; asm("mov.b64 {%0, %1}, %2;" : "=f"(f.x), "=f"(f.y) : "l"(v)); return f;
}
__device__ __forceinline__ void ffma2(ull& d, ull a, ull b) {
    asm("fma.rn.f32x2 %0, %1, %2, %0;" : "+l"(d) : "l"(a), "l"(b));
}
__device__ __forceinline__ float mishf(float x) {
    float sp = (x > 20.f) ? x : log1pf(expf(x));
    return x * tanhf(sp);
}
__device__ __forceinline__ uint32_t s2u(const void* p) {
    uint32_t a;
    asm("{ .reg .u64 t; cvta.to.shared.u64 t, %1; cvt.u32.u64 %0, t; }" : "=r"(a) : "l"(p));
    return a;
}
__device__ __forceinline__ uint32_t packbf2(float a, float b) {
    __nv_bfloat162 v = __floats2bfloat162_rn(a, b);
    return *reinterpret_cast<uint32_t*>(&v);
}
__device__ __forceinline__ float2 unbf2(uint32_t u) {
    __nv_bfloat162 v = *reinterpret_cast<__nv_bfloat162*>(&u);
    return make_float2(__bfloat162float(v.x), __bfloat162float(v.y));
}
__device__ __forceinline__ void hmma(float* acc, uint32_t a0, uint32_t a1,
                                     uint32_t a2, uint32_t a3, uint32_t b0, uint32_t b1) {
    asm volatile("mma.sync.aligned.m16n8k16.row.col.f32.bf16.bf16.f32 "
        "{%0,%1,%2,%3}, {%4,%5,%6,%7}, {%8,%9}, {%0,%1,%2,%3};"
        : "+f"(acc[0]), "+f"(acc[1]), "+f"(acc[2]), "+f"(acc[3])
        : "r"(a0), "r"(a1), "r"(a2), "r"(a3), "r"(b0), "r"(b1));
}
__device__ __forceinline__ void ldsm4(uint32_t* r, uint32_t addr) {
    asm volatile("ldmatrix.sync.aligned.m8n8.x4.shared.b16 {%0,%1,%2,%3}, [%4];"
        : "=r"(r[0]), "=r"(r[1]), "=r"(r[2]), "=r"(r[3]) : "r"(addr));
}
__device__ __forceinline__ uint4 lds128(uint32_t a) {
    uint4 r;
    asm volatile("ld.shared.v4.u32 {%0,%1,%2,%3}, [%4];"
        : "=r"(r.x), "=r"(r.y), "=r"(r.z), "=r"(r.w) : "r"(a));
    return r;
}
__device__ __forceinline__ void cp16(uint32_t d, const void* s) {
    asm volatile("cp.async.cg.shared.global [%0], [%1], 16;" :: "r"(d), "l"(s) : "memory");
}
#define CP_COMMIT() asm volatile("cp.async.commit_group;" ::: "memory")
#define CP_WAIT2()  asm volatile("cp.async.wait_group 2;" ::: "memory")

// split-bf16 MMA GEMM, barrier-free. Warp tile 32 rows x 32 cols.
// A frags via ldmatrix.x4 from smem X images; B via per-lane cp.async ring
// (depth 3, 2 groups in flight). Each lane prefetches exactly the 64B it
// consumes -> no intra-warp synchronization needed.
__device__ __forceinline__ void mma_gemm(
    const uint32_t* __restrict__ gHi, const uint32_t* __restrict__ gLo,
    int nk, uint32_t xh_lane, uint32_t xl_lane, uint32_t bq_lane,
    float acc[2][4][4], int wid, int tx)
{
#pragma unroll
    for (int mi = 0; mi < 2; mi++)
#pragma unroll
        for (int nb = 0; nb < 4; nb++)
#pragma unroll
            for (int e = 0; e < 4; e++) acc[mi][nb][e] = 0.f;

    const uint4* pH = (const uint4*)gHi + (wid * 32 + tx) * 2;
    const uint4* pL = (const uint4*)gLo + (wid * 32 + tx) * 2;
    const uint32_t bq_end = bq_lane + 3 * STAGEB;

    // prologue: stages 0,1 <- kb 0,1
#pragma unroll
    for (int s = 0; s < 2; s++) {
        if (s < nk) {
            uint32_t d = bq_lane + s * STAGEB;
            cp16(d,      pH + s * 1024);
            cp16(d + 16, pH + s * 1024 + 1);
            cp16(d + 32, pL + s * 1024);
            cp16(d + 48, pL + s * 1024 + 1);
        }
        CP_COMMIT();
    }
    uint32_t rd = bq_lane;                  // stage holding kb
    uint32_t wr = bq_lane + 2 * STAGEB;     // stage for kb+2
#pragma unroll 2
    for (int kb = 0; kb < nk; kb++) {
        int pf = kb + 2;
        if (pf < nk) {
            cp16(wr,      pH + pf * 1024);
            cp16(wr + 16, pH + pf * 1024 + 1);
            cp16(wr + 32, pL + pf * 1024);
            cp16(wr + 48, pL + pf * 1024 + 1);
        }
        CP_COMMIT();
        CP_WAIT2();    // in-order retirement: group for kb complete

        uint4 h0 = lds128(rd), h1 = lds128(rd + 16);
        uint4 l0 = lds128(rd + 32), l1 = lds128(rd + 48);

        uint32_t ah[2][4], al[2][4];
#pragma unroll
        for (int mi = 0; mi < 2; mi++) {
            ldsm4(ah[mi], xh_lane + mi * 16 * XSTR + kb * 32);
            ldsm4(al[mi], xl_lane + mi * 16 * XSTR + kb * 32);
        }
        uint32_t bhr[8] = {h0.x, h0.y, h0.z, h0.w, h1.x, h1.y, h1.z, h1.w};
        uint32_t blr[8] = {l0.x, l0.y, l0.z, l0.w, l1.x, l1.y, l1.z, l1.w};
#pragma unroll
        for (int nb = 0; nb < 4; nb++) {
#pragma unroll
            for (int mi = 0; mi < 2; mi++) {
                hmma(acc[mi][nb], ah[mi][0], ah[mi][1], ah[mi][2], ah[mi][3],
                     bhr[2 * nb], bhr[2 * nb + 1]);
                hmma(acc[mi][nb], ah[mi][0], ah[mi][1], ah[mi][2], ah[mi][3],
                     blr[2 * nb], blr[2 * nb + 1]);
                hmma(acc[mi][nb], al[mi][0], al[mi][1], al[mi][2], al[mi][3],
                     bhr[2 * nb], bhr[2 * nb + 1]);
            }
        }
        rd += STAGEB; if (rd == bq_end) rd = bq_lane;
        wr += STAGEB; if (wr == bq_end) wr = bq_lane;
    }
}

// ---------- prep: build frag/lane-order bf16 hi/lo weight images -------------
__global__ void prep_kernel(const float* __restrict__ Wah,
                            const float* __restrict__ Waa,
                            const float* __restrict__ Wb)
{
    int gid = blockIdx.x * 256 + threadIdx.x;
    const float* W; uint32_t *dHi, *dLo; int idx;
    if (gid < 131072)      { W = Wah; dHi = gWahHi; dLo = gWahLo; idx = gid; }
    else if (gid < 262144) { W = Waa; dHi = gWaaHi; dLo = gWaaLo; idx = gid - 131072; }
    else                   { W = Wb;  dHi = gWbHi;  dLo = gWbLo;  idx = gid - 262144; }
    int reg = idx & 1, lane = (idx >> 1) & 31, nb = (idx >> 6) & 63, kb = idx >> 12;
    int tg = lane & 3, gq = lane >> 2;
    int k0 = kb * 16 + 2 * tg + reg * 8;
    int n  = nb * 8 + gq;
    float w0 = W[(size_t)k0 * 512 + n];
    float w1 = W[(size_t)(k0 + 1) * 512 + n];
    __nv_bfloat16 h0 = __float2bfloat16(w0), h1 = __float2bfloat16(w1);
    float l0f = w0 - __bfloat162float(h0), l1f = w1 - __bfloat162float(h1);
    __nv_bfloat162 hv(h0, h1);
    __nv_bfloat162 lv(__float2bfloat16(l0f), __float2bfloat16(l1f));
    int w = nb >> 2, nbi = nb & 3;
    uint32_t nidx = (uint32_t)(((kb * 16 + w) * 32 + lane) * 8 + nbi * 2 + reg);
    dHi[nidx] = *reinterpret_cast<uint32_t*>(&hv);
    dLo[nidx] = *reinterpret_cast<uint32_t*>(&lv);
}

__global__ __launch_bounds__(NTHR)
void holiday_mma_kernel(
    const float* __restrict__ inputs, const float* __restrict__ sku,
    const float* __restrict__ deltas, const float* __restrict__ ln_gamma,
    const float* __restrict__ ln_beta, const float* __restrict__ attn_w,
    const float* __restrict__ Wh, const float* __restrict__ Wa,
    const float* __restrict__ Wo, float* __restrict__ out)
{
    extern __shared__ char smc[];
    float* sWo   = (float*)(smc + OFF_WO);
    float* ps0   = (float*)(smc + OFF_PS0);
    float* ps1   = (float*)(smc + OFF_PS1);
    float* gmaxA = (float*)(smc + OFF_GMX);
    float* sWaWo = (float*)(smc + OFF_WAWO);

    const int tid = threadIdx.x, tx = tid & 31, wid = tid >> 5;   // 16 warps
    const int tg = tx & 3, gq = tx >> 2;
    const int wn0 = wid * 32;
    const int b0 = blockIdx.x * ROWS;
    const unsigned FULL = 0xffffffffu;
    const uint32_t sb = s2u(smc);
    const uint32_t lrow = (tx & 7) + ((tx >> 3) & 1) * 8;
    const uint32_t lcol = (tx >> 4) * 16;
    const uint32_t xh_lane = sb + OFF_XHI + lrow * XSTR + lcol;
    const uint32_t xl_lane = sb + OFF_XLO + lrow * XSTR + lcol;
    const uint32_t bq_lane = sb + OFF_BQ + (wid * 32 + tx) * LSLOT;

    // ---- prologue: Wo, alpha fold, changepoints ----------------------------
    for (int i = tid; i < HID; i += NTHR) sWo[i] = Wo[i];
#pragma unroll
    for (int si = 0; si < 4; si++) {
        int s = wid * 4 + si;
        float p = 0.f;
#pragma unroll
        for (int j = 0; j < 16; j++) {
            int c = tx + 32 * j;
            p = fmaf(__ldg(Wa + s * HID + c), __ldg(Wo + c), p);
        }
#pragma unroll
        for (int o = 16; o > 0; o >>= 1) p += __shfl_xor_sync(FULL, p, o);
        if (tx == 0) sWaWo[s] = p;
    }
    float cps_r;
    {
        float d  = deltas[wid * C + tx];
        float sp = (d > 20.f) ? d : log1pf(expf(d));
        float s  = sp;
#pragma unroll
        for (int o = 1; o < 32; o <<= 1) {
            float v = __shfl_up_sync(FULL, s, o);
            if (tx >= o) s += v;
        }
        cps_r = s * (TMAX / __shfl_sync(FULL, s, 31));
    }

    // ---- stage sku into X images (rows 0..31, k 0..63) ---------------------
    {
        int r = tid >> 4, k0 = (tid & 15) * 4;
        float4 a = *(const float4*)(sku + (size_t)(b0 + r) * SKUD + k0);
        float v[4] = {a.x, a.y, a.z, a.w};
#pragma unroll
        for (int e = 0; e < 2; e++) {
            float v0 = v[2 * e], v1 = v[2 * e + 1];
            __nv_bfloat16 h0 = __float2bfloat16(v0), h1 = __float2bfloat16(v1);
            uint32_t off = r * XSTR + (k0 + 2 * e) * 2;
            __nv_bfloat162 hv2(h0, h1);
            *(uint32_t*)(smc + OFF_XHI + off) = *reinterpret_cast<uint32_t*>(&hv2);
            *(uint32_t*)(smc + OFF_XLO + off) =
                packbf2(v0 - __bfloat162float(h0), v1 - __bfloat162float(h1));
        }
    }
    __syncthreads();

    float acc[2][4][4];

    // ---- GEMM0: beta = sigmoid(sku @ Wb) -> half2 regs ---------------------
    mma_gemm(gWbHi, gWbLo, 4, xh_lane, xl_lane, bq_lane, acc, wid, tx);
    __half2 bh2[2][4][2];
#pragma unroll
    for (int mi = 0; mi < 2; mi++)
#pragma unroll
        for (int nb = 0; nb < 4; nb++) {
            bh2[mi][nb][0] = __floats2half2_rn(
                1.f / (1.f + expf(-acc[mi][nb][0])), 1.f / (1.f + expf(-acc[mi][nb][1])));
            bh2[mi][nb][1] = __floats2half2_rn(
                1.f / (1.f + expf(-acc[mi][nb][2])), 1.f / (1.f + expf(-acc[mi][nb][3])));
        }
    __syncthreads();   // all GEMM0 A-reads done -> stage1 may overwrite X

    // ---- stage 1: features -> X images (h = wid, r = tx) -------------------
    {
        int h = wid;
        float t = inputs[(size_t)(b0 + tx) * H + h];
        float f[C], e[C];
        float mu = 0.f;
#pragma unroll
        for (int c = 0; c < C; c++) {
            float cp = __shfl_sync(FULL, cps_r, c);
            f[c] = fmaxf(t - cp, 0.f); mu += f[c];
        }
        mu *= (1.0f / C);
        float var = 0.f;
#pragma unroll
        for (int c = 0; c < C; c++) { float d = f[c] - mu; var = fmaf(d, d, var); }
        var *= (1.0f / C);
        float rs = rsqrtf(var + LN_EPS);
        float aw = __ldg(attn_w + h) * TEMP_INV;
        float m = -3.4e38f;
#pragma unroll
        for (int c = 0; c < C; c++) {
            float n = fmaf((f[c] - mu) * rs, __ldg(ln_gamma + h * C + c),
                           __ldg(ln_beta + h * C + c));
            f[c] = n;
            m = fmaxf(m, n * aw);
        }
        float s = 0.f;
#pragma unroll
        for (int c = 0; c < C; c++) { e[c] = expf(f[c] * aw - m); s += e[c]; }
        float inv = 1.0f / s;
        ull hid2[16];
#pragma unroll
        for (int d = 0; d < 16; d++) hid2[d] = 0ull;
#pragma unroll
        for (int c = 0; c < C; c++) {
            float a = f[c] * e[c] * inv;
            ull a2 = pack2(a, a);
            const ull* wr = reinterpret_cast<const ull*>(Wh + (h * C + c) * C);
#pragma unroll
            for (int d = 0; d < 16; d++) ffma2(hid2[d], a2, wr[d]);
        }
#pragma unroll
        for (int d = 0; d < 16; d++) {
            float2 hv = unpack2(hid2[d]);
            float v0 = mishf(hv.x), v1 = mishf(hv.y);
            __nv_bfloat16 h0 = __float2bfloat16(v0), h1 = __float2bfloat16(v1);
            uint32_t off = tx * XSTR + (h * 32 + 2 * d) * 2;
            __nv_bfloat162 hv2(h0, h1);
            *(uint32_t*)(smc + OFF_XHI + off) = *reinterpret_cast<uint32_t*>(&hv2);
            *(uint32_t*)(smc + OFF_XLO + off) =
                packbf2(v0 - __bfloat162float(h0), v1 - __bfloat162float(h1));
        }
    }
    __syncthreads();

    // ---- GEMM1: H1 = mish(X @ Wah) -----------------------------------------
    mma_gemm(gWahHi, gWahLo, 32, xh_lane, xl_lane, bq_lane, acc, wid, tx);
    __syncthreads();   // all X reads done -> overwrite with H1
#pragma unroll
    for (int mi = 0; mi < 2; mi++)
#pragma unroll
        for (int nb = 0; nb < 4; nb++)
#pragma unroll
            for (int rb = 0; rb < 2; rb++) {
                int row = mi * 16 + rb * 8 + gq;
                int n = wn0 + nb * 8 + 2 * tg;
                float v0 = mishf(acc[mi][nb][rb * 2]);
                float v1 = mishf(acc[mi][nb][rb * 2 + 1]);
                __nv_bfloat16 h0 = __float2bfloat16(v0), h1 = __float2bfloat16(v1);
                uint32_t off = row * XSTR + n * 2;
                __nv_bfloat162 hv2(h0, h1);
                *(uint32_t*)(smc + OFF_XHI + off) = *reinterpret_cast<uint32_t*>(&hv2);
                *(uint32_t*)(smc + OFF_XLO + off) =
                    packbf2(v0 - __bfloat162float(h0), v1 - __bfloat162float(h1));
            }
    __syncthreads();

    // ---- GEMM2: logits = H1 @ Waa ------------------------------------------
    mma_gemm(gWaaHi, gWaaLo, 32, xh_lane, xl_lane, bq_lane, acc, wid, tx);

    // ---- epilogue -----------------------------------------------------------
    float mx[4] = {-3.4e38f, -3.4e38f, -3.4e38f, -3.4e38f};
#pragma unroll
    for (int mi = 0; mi < 2; mi++)
#pragma unroll
        for (int nb = 0; nb < 4; nb++)
#pragma unroll
            for (int rb = 0; rb < 2; rb++)
                mx[mi * 2 + rb] = fmaxf(mx[mi * 2 + rb],
                    fmaxf(acc[mi][nb][rb * 2], acc[mi][nb][rb * 2 + 1]));
#pragma unroll
    for (int q = 0; q < 4; q++) {
        mx[q] = fmaxf(mx[q], __shfl_xor_sync(FULL, mx[q], 1));
        mx[q] = fmaxf(mx[q], __shfl_xor_sync(FULL, mx[q], 2));
    }
    if (tg == 0) {
#pragma unroll
        for (int q = 0; q < 4; q++)
            ps0[wid * 32 + (q >> 1) * 16 + (q & 1) * 8 + gq] = mx[q];
    }
    __syncthreads();
    if (tid < 32) {
        float m = -3.4e38f;
#pragma unroll
        for (int w = 0; w < 16; w++) m = fmaxf(m, ps0[w * 32 + tid]);
        gmaxA[tid] = m;
    }
    __syncthreads();

    float sv[4] = {0.f, 0.f, 0.f, 0.f}, dv[4] = {0.f, 0.f, 0.f, 0.f};
#pragma unroll
    for (int mi = 0; mi < 2; mi++)
#pragma unroll
        for (int rb = 0; rb < 2; rb++) {
            int row = mi * 16 + rb * 8 + gq;
            float gm = gmaxA[row];
            float s = 0.f, d = 0.f;
#pragma unroll
            for (int nb = 0; nb < 4; nb++) {
                int n = wn0 + nb * 8 + 2 * tg;
                float e0 = expf((acc[mi][nb][rb * 2]     - gm) * TEMP_INV);
                float e1 = expf((acc[mi][nb][rb * 2 + 1] - gm) * TEMP_INV);
                uint32_t off = row * XSTR + n * 2;
                float2 hh = unbf2(*(const uint32_t*)(smc + OFF_XHI + off));
                float2 hl = unbf2(*(const uint32_t*)(smc + OFF_XLO + off));
                float h0 = hh.x + hl.x, h1 = hh.y + hl.y;
                float2 bb = __half22float2(bh2[mi][nb][rb]);
                float2 wo = *(const float2*)(sWo + n);
                s += e0 + e1;
                d = fmaf(e0 * h0 * bb.x, wo.x, d);
                d = fmaf(e1 * h1 * bb.y, wo.y, d);
            }
            sv[mi * 2 + rb] = s; dv[mi * 2 + rb] = d;
        }
#pragma unroll
    for (int q = 0; q < 4; q++) {
        sv[q] += __shfl_xor_sync(FULL, sv[q], 1);
        sv[q] += __shfl_xor_sync(FULL, sv[q], 2);
        dv[q] += __shfl_xor_sync(FULL, dv[q], 1);
        dv[q] += __shfl_xor_sync(FULL, dv[q], 2);
    }
    if (tg == 0) {
#pragma unroll
        for (int q = 0; q < 4; q++) {
            int row = (q >> 1) * 16 + (q & 1) * 8 + gq;
            ps0[wid * 32 + row] = sv[q];
            ps1[wid * 32 + row] = dv[q];
        }
    }
    __syncthreads();
    if (tid < 32) {
        float S = 0.f, D = 0.f;
#pragma unroll
        for (int w = 0; w < 16; w++) { S += ps0[w * 32 + tid]; D += ps1[w * 32 + tid]; }
        float alpha = 0.f;
        const float4* sk4 = (const float4*)(sku + (size_t)(b0 + tid) * SKUD);
#pragma unroll
        for (int q = 0; q < 16; q++) {
            float4 s4 = sk4[q];
            alpha += s4.x * sWaWo[4 * q]     + s4.y * sWaWo[4 * q + 1]
                   + s4.z * sWaWo[4 * q + 2] + s4.w * sWaWo[4 * q + 3];
        }
        out[b0 + tid] = D / S + alpha;
    }
}

extern "C" void kernel_launch(void* const* d_in, const int* in_sizes, int n_in,
                              void* d_out, int out_size)
{
    const float* inputs   = (const float*)d_in[0];
    const float* sku      = (const float*)d_in[1];
    const float* deltas   = (const float*)d_in[2];
    const float* ln_gamma = (const float*)d_in[3];
    const float* ln_beta  = (const float*)d_in[4];
    const float* attn_w   = (const float*)d_in[5];
    const float* Wh       = (const float*)d_in[6];
    const float* Wah      = (const float*)d_in[7];
    const float* Waa      = (const float*)d_in[8];
    const float* Wb       = (const float*)d_in[9];
    const float* Wa       = (const float*)d_in[10];
    const float* Wo       = (const float*)d_in[11];
    float* out = (float*)d_out;

    int B = in_sizes[0] / H;
    prep_kernel<<<1088, 256>>>(Wah, Waa, Wb);
    cudaFuncSetAttribute(holiday_mma_kernel,
                         cudaFuncAttributeMaxDynamicSharedMemorySize, SMEM_BYTES);
    holiday_mma_kernel<<<B / ROWS, NTHR, SMEM_BYTES>>>(
        inputs, sku, deltas, ln_gamma, ln_beta, attn_w, Wh, Wa, Wo, out);
}

// round 15
// speedup vs baseline: 1.7603x; 1.7603x over previous
#include <cuda_runtime.h>
#include <cuda_fp16.h>
#include <cuda_bf16.h>
#include <math.h>
#include <stdint.h>

// prep-built weight images, LDG.128-friendly order:
// u32 idx = ((kb*16 + warp)*32 + lane)*8 + nbi*2 + reg   (nbi = nb within warp)
__device__ __align__(16) uint32_t gWahHi[131072];
__device__ __align__(16) uint32_t gWahLo[131072];
__device__ __align__(16) uint32_t gWaaHi[131072];
__device__ __align__(16) uint32_t gWaaLo[131072];
__device__ __align__(16) uint32_t gWbHi [16384];
__device__ __align__(16) uint32_t gWbLo [16384];

namespace {
constexpr int H = 16, C = 32, HID = 512, SKUD = 64, ROWS = 32, NTHR = 512;
constexpr float TEMP_INV = 1.0f / 0.7f, TMAX = 365.0f, LN_EPS = 1e-3f;
constexpr int XSTR = 1040;                 // X image row stride in bytes (520 bf16)
// smem byte offsets
constexpr int OFF_XHI = 0;                 // 32*1040 = 33280
constexpr int OFF_XLO = 33280;
constexpr int OFF_WO  = 66560;             // 512 f32
constexpr int OFF_PS0 = 68608;             // 16*32 f32
constexpr int OFF_PS1 = 70656;             // 16*32 f32
constexpr int OFF_GMX = 72704;             // 32 f32
constexpr int OFF_WAWO= 72832;             // 64 f32
constexpr int SMEM_BYTES = 73088;
}

using ull = unsigned long long;

__device__ __forceinline__ ull pack2(float x, float y) {
    ull r; asm("mov.b64 %0, {%1, %2};" : "=l"(r) : "f"(x), "f"(y)); return r;
}
__device__ __forceinline__ float2 unpack2(ull v) {
    float2 f; asm("mov.b64 {%0, %1}, %2;" : "=f"(f.x), "=f"(f.y) : "l"(v)); return f;
}
__device__ __forceinline__ void ffma2(ull& d, ull a, ull b) {
    asm("fma.rn.f32x2 %0, %1, %2, %0;" : "+l"(d) : "l"(a), "l"(b));
}
__device__ __forceinline__ float mishf(float x) {
    float sp = (x > 20.f) ? x : log1pf(expf(x));
    return x * tanhf(sp);
}
__device__ __forceinline__ uint32_t s2u(const void* p) {
    uint32_t a;
    asm("{ .reg .u64 t; cvta.to.shared.u64 t, %1; cvt.u32.u64 %0, t; }" : "=r"(a) : "l"(p));
    return a;
}
__device__ __forceinline__ uint32_t packbf2(float a, float b) {
    __nv_bfloat162 v = __floats2bfloat162_rn(a, b);
    return *reinterpret_cast<uint32_t*>(&v);
}
__device__ __forceinline__ float2 unbf2(uint32_t u) {
    __nv_bfloat162 v = *reinterpret_cast<__nv_bfloat162*>(&u);
    return make_float2(__bfloat162float(v.x), __bfloat162float(v.y));
}
// NON-volatile: pure register op; let ptxas schedule/pipe HMMAs freely.
__device__ __forceinline__ void hmma(float* acc, uint32_t a0, uint32_t a1,
                                     uint32_t a2, uint32_t a3, uint32_t b0, uint32_t b1) {
    asm("mma.sync.aligned.m16n8k16.row.col.f32.bf16.bf16.f32 "
        "{%0,%1,%2,%3}, {%4,%5,%6,%7}, {%8,%9}, {%0,%1,%2,%3};"
        : "+f"(acc[0]), "+f"(acc[1]), "+f"(acc[2]), "+f"(acc[3])
        : "r"(a0), "r"(a1), "r"(a2), "r"(a3), "r"(b0), "r"(b1));
}
__device__ __forceinline__ void ldsm4(uint32_t* r, uint32_t addr) {
    asm volatile("ldmatrix.sync.aligned.m8n8.x4.shared.b16 {%0,%1,%2,%3}, [%4];"
        : "=r"(r[0]), "=r"(r[1]), "=r"(r[2]), "=r"(r[3]) : "r"(addr));
}

// split-bf16 MMA GEMM, barrier-free. Warp tile 32 rows x 32 cols.
// A frags via ldmatrix.x4 from smem X images; B frag-order from global
// (L1-cached __ldg LDG.128), register double-buffered across kb.
// HMMAs issued PASS-MAJOR: 8 independent accs between each acc reuse.
__device__ __forceinline__ void mma_gemm(
    const uint32_t* __restrict__ gHi, const uint32_t* __restrict__ gLo,
    int nk, uint32_t xh_lane, uint32_t xl_lane,
    float acc[2][4][4], int wid, int tx)
{
#pragma unroll
    for (int mi = 0; mi < 2; mi++)
#pragma unroll
        for (int nb = 0; nb < 4; nb++)
#pragma unroll
            for (int e = 0; e < 4; e++) acc[mi][nb][e] = 0.f;

    const uint4* pH = (const uint4*)gHi;
    const uint4* pL = (const uint4*)gLo;
    const int bidx = (wid * 32 + tx) * 2;   // uint4 index; +1024 per kb

    uint4 bh[2][2], bl[2][2];
    bh[0][0] = __ldg(pH + bidx);     bh[0][1] = __ldg(pH + bidx + 1);
    bl[0][0] = __ldg(pL + bidx);     bl[0][1] = __ldg(pL + bidx + 1);
#pragma unroll 2
    for (int kb = 0; kb < nk; kb++) {
        int cur = kb & 1, nxt = cur ^ 1;
        if (kb + 1 < nk) {
            int p = bidx + (kb + 1) * 1024;
            bh[nxt][0] = __ldg(pH + p);     bh[nxt][1] = __ldg(pH + p + 1);
            bl[nxt][0] = __ldg(pL + p);     bl[nxt][1] = __ldg(pL + p + 1);
        }
        uint32_t ah[2][4], al[2][4];
#pragma unroll
        for (int mi = 0; mi < 2; mi++) {
            ldsm4(ah[mi], xh_lane + mi * 16 * XSTR + kb * 32);
            ldsm4(al[mi], xl_lane + mi * 16 * XSTR + kb * 32);
        }
        uint32_t bhr[8], blr[8];
        bhr[0] = bh[cur][0].x; bhr[1] = bh[cur][0].y; bhr[2] = bh[cur][0].z; bhr[3] = bh[cur][0].w;
        bhr[4] = bh[cur][1].x; bhr[5] = bh[cur][1].y; bhr[6] = bh[cur][1].z; bhr[7] = bh[cur][1].w;
        blr[0] = bl[cur][0].x; blr[1] = bl[cur][0].y; blr[2] = bl[cur][0].z; blr[3] = bl[cur][0].w;
        blr[4] = bl[cur][1].x; blr[5] = bl[cur][1].y; blr[6] = bl[cur][1].z; blr[7] = bl[cur][1].w;
        // pass 1: hi(A) * hi(B) — 8 independent acc chains
#pragma unroll
        for (int nb = 0; nb < 4; nb++)
#pragma unroll
            for (int mi = 0; mi < 2; mi++)
                hmma(acc[mi][nb], ah[mi][0], ah[mi][1], ah[mi][2], ah[mi][3],
                     bhr[2 * nb], bhr[2 * nb + 1]);
        // pass 2: hi(A) * lo(B)
#pragma unroll
        for (int nb = 0; nb < 4; nb++)
#pragma unroll
            for (int mi = 0; mi < 2; mi++)
                hmma(acc[mi][nb], ah[mi][0], ah[mi][1], ah[mi][2], ah[mi][3],
                     blr[2 * nb], blr[2 * nb + 1]);
        // pass 3: lo(A) * hi(B)
#pragma unroll
        for (int nb = 0; nb < 4; nb++)
#pragma unroll
            for (int mi = 0; mi < 2; mi++)
                hmma(acc[mi][nb], al[mi][0], al[mi][1], al[mi][2], al[mi][3],
                     bhr[2 * nb], bhr[2 * nb + 1]);
    }
}

// ---------- prep: build LDG.128-order bf16 hi/lo weight images ---------------
__global__ void prep_kernel(const float* __restrict__ Wah,
                            const float* __restrict__ Waa,
                            const float* __restrict__ Wb)
{
    int gid = blockIdx.x * 256 + threadIdx.x;
    const float* W; uint32_t *dHi, *dLo; int idx;
    if (gid < 131072)      { W = Wah; dHi = gWahHi; dLo = gWahLo; idx = gid; }
    else if (gid < 262144) { W = Waa; dHi = gWaaHi; dLo = gWaaLo; idx = gid - 131072; }
    else                   { W = Wb;  dHi = gWbHi;  dLo = gWbLo;  idx = gid - 262144; }
    int reg = idx & 1, lane = (idx >> 1) & 31, nb = (idx >> 6) & 63, kb = idx >> 12;
    int tg = lane & 3, gq = lane >> 2;
    int k0 = kb * 16 + 2 * tg + reg * 8;
    int n  = nb * 8 + gq;
    float w0 = W[(size_t)k0 * 512 + n];
    float w1 = W[(size_t)(k0 + 1) * 512 + n];
    __nv_bfloat16 h0 = __float2bfloat16(w0), h1 = __float2bfloat16(w1);
    float l0f = w0 - __bfloat162float(h0), l1f = w1 - __bfloat162float(h1);
    __nv_bfloat162 hv(h0, h1);
    __nv_bfloat162 lv(__float2bfloat16(l0f), __float2bfloat16(l1f));
    int w = nb >> 2, nbi = nb & 3;
    uint32_t nidx = (uint32_t)(((kb * 16 + w) * 32 + lane) * 8 + nbi * 2 + reg);
    dHi[nidx] = *reinterpret_cast<uint32_t*>(&hv);
    dLo[nidx] = *reinterpret_cast<uint32_t*>(&lv);
}

__global__ __launch_bounds__(NTHR)
void holiday_mma_kernel(
    const float* __restrict__ inputs, const float* __restrict__ sku,
    const float* __restrict__ deltas, const float* __restrict__ ln_gamma,
    const float* __restrict__ ln_beta, const float* __restrict__ attn_w,
    const float* __restrict__ Wh, const float* __restrict__ Wa,
    const float* __restrict__ Wo, float* __restrict__ out)
{
    extern __shared__ char smc[];
    float* sWo   = (float*)(smc + OFF_WO);
    float* ps0   = (float*)(smc + OFF_PS0);
    float* ps1   = (float*)(smc + OFF_PS1);
    float* gmaxA = (float*)(smc + OFF_GMX);
    float* sWaWo = (float*)(smc + OFF_WAWO);

    const int tid = threadIdx.x, tx = tid & 31, wid = tid >> 5;   // 16 warps
    const int tg = tx & 3, gq = tx >> 2;
    const int wn0 = wid * 32;
    const int b0 = blockIdx.x * ROWS;
    const unsigned FULL = 0xffffffffu;
    const uint32_t sb = s2u(smc);
    // ldmatrix lane base address (mi=0, kb=0): matrices {rows0-7 klo, rows8-15 klo,
    // rows0-7 khi, rows8-15 khi}
    const uint32_t lrow = (tx & 7) + ((tx >> 3) & 1) * 8;
    const uint32_t lcol = (tx >> 4) * 16;
    const uint32_t xh_lane = sb + OFF_XHI + lrow * XSTR + lcol;
    const uint32_t xl_lane = sb + OFF_XLO + lrow * XSTR + lcol;

    // ---- prologue: Wo, alpha fold, changepoints ----------------------------
    for (int i = tid; i < HID; i += NTHR) sWo[i] = Wo[i];
#pragma unroll
    for (int si = 0; si < 4; si++) {
        int s = wid * 4 + si;
        float p = 0.f;
#pragma unroll
        for (int j = 0; j < 16; j++) {
            int c = tx + 32 * j;
            p = fmaf(__ldg(Wa + s * HID + c), __ldg(Wo + c), p);
        }
#pragma unroll
        for (int o = 16; o > 0; o >>= 1) p += __shfl_xor_sync(FULL, p, o);
        if (tx == 0) sWaWo[s] = p;
    }
    float cps_r;
    {
        float d  = deltas[wid * C + tx];
        float sp = (d > 20.f) ? d : log1pf(expf(d));
        float s  = sp;
#pragma unroll
        for (int o = 1; o < 32; o <<= 1) {
            float v = __shfl_up_sync(FULL, s, o);
            if (tx >= o) s += v;
        }
        cps_r = s * (TMAX / __shfl_sync(FULL, s, 31));
    }

    // ---- stage sku into X images (rows 0..31, k 0..63) ---------------------
    {
        int r = tid >> 4, k0 = (tid & 15) * 4;
        float4 a = *(const float4*)(sku + (size_t)(b0 + r) * SKUD + k0);
        float v[4] = {a.x, a.y, a.z, a.w};
#pragma unroll
        for (int e = 0; e < 2; e++) {
            float v0 = v[2 * e], v1 = v[2 * e + 1];
            __nv_bfloat16 h0 = __float2bfloat16(v0), h1 = __float2bfloat16(v1);
            uint32_t off = r * XSTR + (k0 + 2 * e) * 2;
            __nv_bfloat162 hv2(h0, h1);
            *(uint32_t*)(smc + OFF_XHI + off) = *reinterpret_cast<uint32_t*>(&hv2);
            *(uint32_t*)(smc + OFF_XLO + off) =
                packbf2(v0 - __bfloat162float(h0), v1 - __bfloat162float(h1));
        }
    }
    __syncthreads();

    float acc[2][4][4];

    // ---- GEMM0: beta = sigmoid(sku @ Wb) -> half2 regs ---------------------
    mma_gemm(gWbHi, gWbLo, 4, xh_lane, xl_lane, acc, wid, tx);
    __half2 bh2[2][4][2];
#pragma unroll
    for (int mi = 0; mi < 2; mi++)
#pragma unroll
        for (int nb = 0; nb < 4; nb++) {
            bh2[mi][nb][0] = __floats2half2_rn(
                1.f / (1.f + expf(-acc[mi][nb][0])), 1.f / (1.f + expf(-acc[mi][nb][1])));
            bh2[mi][nb][1] = __floats2half2_rn(
                1.f / (1.f + expf(-acc[mi][nb][2])), 1.f / (1.f + expf(-acc[mi][nb][3])));
        }
    __syncthreads();   // all GEMM0 A-reads done -> stage1 may overwrite X

    // ---- stage 1: features -> X images (h = wid, r = tx) -------------------
    {
        int h = wid;
        float t = inputs[(size_t)(b0 + tx) * H + h];
        float f[C], e[C];
        float mu = 0.f;
#pragma unroll
        for (int c = 0; c < C; c++) {
            float cp = __shfl_sync(FULL, cps_r, c);
            f[c] = fmaxf(t - cp, 0.f); mu += f[c];
        }
        mu *= (1.0f / C);
        float var = 0.f;
#pragma unroll
        for (int c = 0; c < C; c++) { float d = f[c] - mu; var = fmaf(d, d, var); }
        var *= (1.0f / C);
        float rs = rsqrtf(var + LN_EPS);
        float aw = __ldg(attn_w + h) * TEMP_INV;
        float m = -3.4e38f;
#pragma unroll
        for (int c = 0; c < C; c++) {
            float n = fmaf((f[c] - mu) * rs, __ldg(ln_gamma + h * C + c),
                           __ldg(ln_beta + h * C + c));
            f[c] = n;
            m = fmaxf(m, n * aw);
        }
        float s = 0.f;
#pragma unroll
        for (int c = 0; c < C; c++) { e[c] = expf(f[c] * aw - m); s += e[c]; }
        float inv = 1.0f / s;
        ull hid2[16];
#pragma unroll
        for (int d = 0; d < 16; d++) hid2[d] = 0ull;
#pragma unroll
        for (int c = 0; c < C; c++) {
            float a = f[c] * e[c] * inv;
            ull a2 = pack2(a, a);
            const ull* wr = reinterpret_cast<const ull*>(Wh + (h * C + c) * C);
#pragma unroll
            for (int d = 0; d < 16; d++) ffma2(hid2[d], a2, wr[d]);
        }
#pragma unroll
        for (int d = 0; d < 16; d++) {
            float2 hv = unpack2(hid2[d]);
            float v0 = mishf(hv.x), v1 = mishf(hv.y);
            __nv_bfloat16 h0 = __float2bfloat16(v0), h1 = __float2bfloat16(v1);
            uint32_t off = tx * XSTR + (h * 32 + 2 * d) * 2;
            __nv_bfloat162 hv2(h0, h1);
            *(uint32_t*)(smc + OFF_XHI + off) = *reinterpret_cast<uint32_t*>(&hv2);
            *(uint32_t*)(smc + OFF_XLO + off) =
                packbf2(v0 - __bfloat162float(h0), v1 - __bfloat162float(h1));
        }
    }
    __syncthreads();

    // ---- GEMM1: H1 = mish(X @ Wah) -----------------------------------------
    mma_gemm(gWahHi, gWahLo, 32, xh_lane, xl_lane, acc, wid, tx);
    __syncthreads();   // all X reads done -> overwrite with H1
#pragma unroll
    for (int mi = 0; mi < 2; mi++)
#pragma unroll
        for (int nb = 0; nb < 4; nb++)
#pragma unroll
            for (int rb = 0; rb < 2; rb++) {
                int row = mi * 16 + rb * 8 + gq;
                int n = wn0 + nb * 8 + 2 * tg;
                float v0 = mishf(acc[mi][nb][rb * 2]);
                float v1 = mishf(acc[mi][nb][rb * 2 + 1]);
                __nv_bfloat16 h0 = __float2bfloat16(v0), h1 = __float2bfloat16(v1);
                uint32_t off = row * XSTR + n * 2;
                __nv_bfloat162 hv2(h0, h1);
                *(uint32_t*)(smc + OFF_XHI + off) = *reinterpret_cast<uint32_t*>(&hv2);
                *(uint32_t*)(smc + OFF_XLO + off) =
                    packbf2(v0 - __bfloat162float(h0), v1 - __bfloat162float(h1));
            }
    __syncthreads();

    // ---- GEMM2: logits = H1 @ Waa ------------------------------------------
    mma_gemm(gWaaHi, gWaaLo, 32, xh_lane, xl_lane, acc, wid, tx);

    // ---- epilogue -----------------------------------------------------------
    float mx[4] = {-3.4e38f, -3.4e38f, -3.4e38f, -3.4e38f};
#pragma unroll
    for (int mi = 0; mi < 2; mi++)
#pragma unroll
        for (int nb = 0; nb < 4; nb++)
#pragma unroll
            for (int rb = 0; rb < 2; rb++)
                mx[mi * 2 + rb] = fmaxf(mx[mi * 2 + rb],
                    fmaxf(acc[mi][nb][rb * 2], acc[mi][nb][rb * 2 + 1]));
#pragma unroll
    for (int q = 0; q < 4; q++) {
        mx[q] = fmaxf(mx[q], __shfl_xor_sync(FULL, mx[q], 1));
        mx[q] = fmaxf(mx[q], __shfl_xor_sync(FULL, mx[q], 2));
    }
    if (tg == 0) {
#pragma unroll
        for (int q = 0; q < 4; q++)
            ps0[wid * 32 + (q >> 1) * 16 + (q & 1) * 8 + gq] = mx[q];
    }
    __syncthreads();
    if (tid < 32) {
        float m = -3.4e38f;
#pragma unroll
        for (int w = 0; w < 16; w++) m = fmaxf(m, ps0[w * 32 + tid]);
        gmaxA[tid] = m;
    }
    __syncthreads();

    float sv[4] = {0.f, 0.f, 0.f, 0.f}, dv[4] = {0.f, 0.f, 0.f, 0.f};
#pragma unroll
    for (int mi = 0; mi < 2; mi++)
#pragma unroll
        for (int rb = 0; rb < 2; rb++) {
            int row = mi * 16 + rb * 8 + gq;
            float gm = gmaxA[row];
            float s = 0.f, d = 0.f;
#pragma unroll
            for (int nb = 0; nb < 4; nb++) {
                int n = wn0 + nb * 8 + 2 * tg;
                float e0 = expf((acc[mi][nb][rb * 2]     - gm) * TEMP_INV);
                float e1 = expf((acc[mi][nb][rb * 2 + 1] - gm) * TEMP_INV);
                uint32_t off = row * XSTR + n * 2;
                float2 hh = unbf2(*(const uint32_t*)(smc + OFF_XHI + off));
                float2 hl = unbf2(*(const uint32_t*)(smc + OFF_XLO + off));
                float h0 = hh.x + hl.x, h1 = hh.y + hl.y;
                float2 bb = __half22float2(bh2[mi][nb][rb]);
                float2 wo = *(const float2*)(sWo + n);
                s += e0 + e1;
                d = fmaf(e0 * h0 * bb.x, wo.x, d);
                d = fmaf(e1 * h1 * bb.y, wo.y, d);
            }
            sv[mi * 2 + rb] = s; dv[mi * 2 + rb] = d;
        }
#pragma unroll
    for (int q = 0; q < 4; q++) {
        sv[q] += __shfl_xor_sync(FULL, sv[q], 1);
        sv[q] += __shfl_xor_sync(FULL, sv[q], 2);
        dv[q] += __shfl_xor_sync(FULL, dv[q], 1);
        dv[q] += __shfl_xor_sync(FULL, dv[q], 2);
    }
    if (tg == 0) {
#pragma unroll
        for (int q = 0; q < 4; q++) {
            int row = (q >> 1) * 16 + (q & 1) * 8 + gq;
            ps0[wid * 32 + row] = sv[q];
            ps1[wid * 32 + row] = dv[q];
        }
    }
    __syncthreads();
    if (tid < 32) {
        float S = 0.f, D = 0.f;
#pragma unroll
        for (int w = 0; w < 16; w++) { S += ps0[w * 32 + tid]; D += ps1[w * 32 + tid]; }
        float alpha = 0.f;
        const float4* sk4 = (const float4*)(sku + (size_t)(b0 + tid) * SKUD);
#pragma unroll
        for (int q = 0; q < 16; q++) {
            float4 s4 = sk4[q];
            alpha += s4.x * sWaWo[4 * q]     + s4.y * sWaWo[4 * q + 1]
                   + s4.z * sWaWo[4 * q + 2] + s4.w * sWaWo[4 * q + 3];
        }
        out[b0 + tid] = D / S + alpha;
    }
}

extern "C" void kernel_launch(void* const* d_in, const int* in_sizes, int n_in,
                              void* d_out, int out_size)
{
    const float* inputs   = (const float*)d_in[0];
    const float* sku      = (const float*)d_in[1];
    const float* deltas   = (const float*)d_in[2];
    const float* ln_gamma = (const float*)d_in[3];
    const float* ln_beta  = (const float*)d_in[4];
    const float* attn_w   = (const float*)d_in[5];
    const float* Wh       = (const float*)d_in[6];
    const float* Wah      = (const float*)d_in[7];
    const float* Waa      = (const float*)d_in[8];
    const float* Wb       = (const float*)d_in[9];
    const float* Wa       = (const float*)d_in[10];
    const float* Wo       = (const float*)d_in[11];
    float* out = (float*)d_out;

    int B = in_sizes[0] / H;
    prep_kernel<<<1088, 256>>>(Wah, Waa, Wb);
    cudaFuncSetAttribute(holiday_mma_kernel,
                         cudaFuncAttributeMaxDynamicSharedMemorySize, SMEM_BYTES);
    holiday_mma_kernel<<<B / ROWS, NTHR, SMEM_BYTES>>>(
        inputs, sku, deltas, ln_gamma, ln_beta, attn_w, Wh, Wa, Wo, out);
}

// round 16
// speedup vs baseline: 2.5357x; 1.4405x over previous
#include <cuda_runtime.h>
#include <cuda_fp16.h>
#include <cuda_bf16.h>
#include <math.h>
#include <stdint.h>

// prep-built bf16 weight image, LDG.128-friendly order:
// u32 idx = ((kb*16 + warp)*32 + lane)*8 + nbi*2 + reg   (nbi = nb within warp)
__device__ __align__(16) uint32_t gWahHi[131072];
__device__ __align__(16) uint32_t gWaaHi[131072];
__device__ __align__(16) uint32_t gWbHi [16384];

namespace {
constexpr int H = 16, C = 32, HID = 512, SKUD = 64, ROWS = 32, NTHR = 512;
constexpr float TEMP_INV = 1.0f / 0.7f, TMAX = 365.0f, LN_EPS = 1e-3f;
constexpr int XSTR = 1040;                 // X image row stride in bytes (520 bf16)
// smem byte offsets
constexpr int OFF_XHI = 0;                 // 32*1040 = 33280
constexpr int OFF_WO  = 33280;             // 512 f32
constexpr int OFF_PS0 = 35328;             // 16*32 f32
constexpr int OFF_PS1 = 37376;             // 16*32 f32
constexpr int OFF_GMX = 39424;             // 32 f32
constexpr int OFF_WAWO= 39552;             // 64 f32
constexpr int SMEM_BYTES = 39808;
}

using ull = unsigned long long;

__device__ __forceinline__ ull pack2(float x, float y) {
    ull r; asm("mov.b64 %0, {%1, %2};" : "=l"(r) : "f"(x), "f"(y)); return r;
}
__device__ __forceinline__ float2 unpack2(ull v) {
    float2 f; asm("mov.b64 {%0, %1}, %2;" : "=f"(f.x), "=f"(f.y) : "l"(v)); return f;
}
__device__ __forceinline__ void ffma2(ull& d, ull a, ull b) {
    asm("fma.rn.f32x2 %0, %1, %2, %0;" : "+l"(d) : "l"(a), "l"(b));
}
__device__ __forceinline__ float mishf(float x) {
    float sp = (x > 20.f) ? x : log1pf(expf(x));
    return x * tanhf(sp);
}
__device__ __forceinline__ uint32_t s2u(const void* p) {
    uint32_t a;
    asm("{ .reg .u64 t; cvta.to.shared.u64 t, %1; cvt.u32.u64 %0, t; }" : "=r"(a) : "l"(p));
    return a;
}
__device__ __forceinline__ float2 unbf2(uint32_t u) {
    __nv_bfloat162 v = *reinterpret_cast<__nv_bfloat162*>(&u);
    return make_float2(__bfloat162float(v.x), __bfloat162float(v.y));
}
__device__ __forceinline__ void hmma(float* acc, uint32_t a0, uint32_t a1,
                                     uint32_t a2, uint32_t a3, uint32_t b0, uint32_t b1) {
    asm("mma.sync.aligned.m16n8k16.row.col.f32.bf16.bf16.f32 "
        "{%0,%1,%2,%3}, {%4,%5,%6,%7}, {%8,%9}, {%0,%1,%2,%3};"
        : "+f"(acc[0]), "+f"(acc[1]), "+f"(acc[2]), "+f"(acc[3])
        : "r"(a0), "r"(a1), "r"(a2), "r"(a3), "r"(b0), "r"(b1));
}
__device__ __forceinline__ void ldsm4(uint32_t* r, uint32_t addr) {
    asm volatile("ldmatrix.sync.aligned.m8n8.x4.shared.b16 {%0,%1,%2,%3}, [%4];"
        : "=r"(r[0]), "=r"(r[1]), "=r"(r[2]), "=r"(r[3]) : "r"(addr));
}

// single-pass bf16 MMA GEMM, barrier-free. Warp tile 32 rows x 32 cols.
// A frags via ldmatrix.x4 from smem X image; B frag-order from global
// (L1-cached __ldg LDG.128), register double-buffered across kb.
__device__ __forceinline__ void mma_gemm(
    const uint32_t* __restrict__ gHi, int nk,
    uint32_t xh_lane, float acc[2][4][4], int wid, int tx)
{
#pragma unroll
    for (int mi = 0; mi < 2; mi++)
#pragma unroll
        for (int nb = 0; nb < 4; nb++)
#pragma unroll
            for (int e = 0; e < 4; e++) acc[mi][nb][e] = 0.f;

    const uint4* pH = (const uint4*)gHi;
    const int bidx = (wid * 32 + tx) * 2;   // uint4 index; +1024 per kb

    uint4 bh[2][2];
    bh[0][0] = __ldg(pH + bidx);     bh[0][1] = __ldg(pH + bidx + 1);
#pragma unroll 2
    for (int kb = 0; kb < nk; kb++) {
        int cur = kb & 1, nxt = cur ^ 1;
        if (kb + 1 < nk) {
            int p = bidx + (kb + 1) * 1024;
            bh[nxt][0] = __ldg(pH + p);     bh[nxt][1] = __ldg(pH + p + 1);
        }
        uint32_t ah[2][4];
#pragma unroll
        for (int mi = 0; mi < 2; mi++)
            ldsm4(ah[mi], xh_lane + mi * 16 * XSTR + kb * 32);
        uint32_t bhr[8];
        bhr[0] = bh[cur][0].x; bhr[1] = bh[cur][0].y; bhr[2] = bh[cur][0].z; bhr[3] = bh[cur][0].w;
        bhr[4] = bh[cur][1].x; bhr[5] = bh[cur][1].y; bhr[6] = bh[cur][1].z; bhr[7] = bh[cur][1].w;
#pragma unroll
        for (int nb = 0; nb < 4; nb++)
#pragma unroll
            for (int mi = 0; mi < 2; mi++)
                hmma(acc[mi][nb], ah[mi][0], ah[mi][1], ah[mi][2], ah[mi][3],
                     bhr[2 * nb], bhr[2 * nb + 1]);
    }
}

// ---------- prep: build LDG.128-order bf16 weight images ---------------------
__global__ void prep_kernel(const float* __restrict__ Wah,
                            const float* __restrict__ Waa,
                            const float* __restrict__ Wb)
{
    int gid = blockIdx.x * 256 + threadIdx.x;
    const float* W; uint32_t* dHi; int idx;
    if (gid < 131072)      { W = Wah; dHi = gWahHi; idx = gid; }
    else if (gid < 262144) { W = Waa; dHi = gWaaHi; idx = gid - 131072; }
    else                   { W = Wb;  dHi = gWbHi;  idx = gid - 262144; }
    int reg = idx & 1, lane = (idx >> 1) & 31, nb = (idx >> 6) & 63, kb = idx >> 12;
    int tg = lane & 3, gq = lane >> 2;
    int k0 = kb * 16 + 2 * tg + reg * 8;
    int n  = nb * 8 + gq;
    float w0 = W[(size_t)k0 * 512 + n];
    float w1 = W[(size_t)(k0 + 1) * 512 + n];
    __nv_bfloat162 hv(__float2bfloat16(w0), __float2bfloat16(w1));
    int w = nb >> 2, nbi = nb & 3;
    uint32_t nidx = (uint32_t)(((kb * 16 + w) * 32 + lane) * 8 + nbi * 2 + reg);
    dHi[nidx] = *reinterpret_cast<uint32_t*>(&hv);
}

__global__ __launch_bounds__(NTHR)
void holiday_mma_kernel(
    const float* __restrict__ inputs, const float* __restrict__ sku,
    const float* __restrict__ deltas, const float* __restrict__ ln_gamma,
    const float* __restrict__ ln_beta, const float* __restrict__ attn_w,
    const float* __restrict__ Wh, const float* __restrict__ Wa,
    const float* __restrict__ Wo, float* __restrict__ out)
{
    extern __shared__ char smc[];
    float* sWo   = (float*)(smc + OFF_WO);
    float* ps0   = (float*)(smc + OFF_PS0);
    float* ps1   = (float*)(smc + OFF_PS1);
    float* gmaxA = (float*)(smc + OFF_GMX);
    float* sWaWo = (float*)(smc + OFF_WAWO);

    const int tid = threadIdx.x, tx = tid & 31, wid = tid >> 5;   // 16 warps
    const int tg = tx & 3, gq = tx >> 2;
    const int wn0 = wid * 32;
    const int b0 = blockIdx.x * ROWS;
    const unsigned FULL = 0xffffffffu;
    const uint32_t sb = s2u(smc);
    const uint32_t lrow = (tx & 7) + ((tx >> 3) & 1) * 8;
    const uint32_t lcol = (tx >> 4) * 16;
    const uint32_t xh_lane = sb + OFF_XHI + lrow * XSTR + lcol;

    // ---- prologue: Wo, alpha fold, changepoints ----------------------------
    for (int i = tid; i < HID; i += NTHR) sWo[i] = Wo[i];
#pragma unroll
    for (int si = 0; si < 4; si++) {
        int s = wid * 4 + si;
        float p = 0.f;
#pragma unroll
        for (int j = 0; j < 16; j++) {
            int c = tx + 32 * j;
            p = fmaf(__ldg(Wa + s * HID + c), __ldg(Wo + c), p);
        }
#pragma unroll
        for (int o = 16; o > 0; o >>= 1) p += __shfl_xor_sync(FULL, p, o);
        if (tx == 0) sWaWo[s] = p;
    }
    float cps_r;
    {
        float d  = deltas[wid * C + tx];
        float sp = (d > 20.f) ? d : log1pf(expf(d));
        float s  = sp;
#pragma unroll
        for (int o = 1; o < 32; o <<= 1) {
            float v = __shfl_up_sync(FULL, s, o);
            if (tx >= o) s += v;
        }
        cps_r = s * (TMAX / __shfl_sync(FULL, s, 31));
    }

    // ---- stage sku into X image (rows 0..31, k 0..63) ----------------------
    {
        int r = tid >> 4, k0 = (tid & 15) * 4;
        float4 a = *(const float4*)(sku + (size_t)(b0 + r) * SKUD + k0);
        __nv_bfloat162 p0(__float2bfloat16(a.x), __float2bfloat16(a.y));
        __nv_bfloat162 p1(__float2bfloat16(a.z), __float2bfloat16(a.w));
        uint32_t off = r * XSTR + k0 * 2;
        *(uint32_t*)(smc + OFF_XHI + off)     = *reinterpret_cast<uint32_t*>(&p0);
        *(uint32_t*)(smc + OFF_XHI + off + 4) = *reinterpret_cast<uint32_t*>(&p1);
    }
    __syncthreads();

    float acc[2][4][4];

    // ---- GEMM0: beta = sigmoid(sku @ Wb) -> half2 regs ---------------------
    mma_gemm(gWbHi, 4, xh_lane, acc, wid, tx);
    __half2 bh2[2][4][2];
#pragma unroll
    for (int mi = 0; mi < 2; mi++)
#pragma unroll
        for (int nb = 0; nb < 4; nb++) {
            bh2[mi][nb][0] = __floats2half2_rn(
                1.f / (1.f + expf(-acc[mi][nb][0])), 1.f / (1.f + expf(-acc[mi][nb][1])));
            bh2[mi][nb][1] = __floats2half2_rn(
                1.f / (1.f + expf(-acc[mi][nb][2])), 1.f / (1.f + expf(-acc[mi][nb][3])));
        }
    __syncthreads();   // all GEMM0 A-reads done -> stage1 may overwrite X

    // ---- stage 1: features -> X image (h = wid, r = tx) --------------------
    {
        int h = wid;
        float t = inputs[(size_t)(b0 + tx) * H + h];
        float f[C], e[C];
        float mu = 0.f;
#pragma unroll
        for (int c = 0; c < C; c++) {
            float cp = __shfl_sync(FULL, cps_r, c);
            f[c] = fmaxf(t - cp, 0.f); mu += f[c];
        }
        mu *= (1.0f / C);
        float var = 0.f;
#pragma unroll
        for (int c = 0; c < C; c++) { float d = f[c] - mu; var = fmaf(d, d, var); }
        var *= (1.0f / C);
        float rs = rsqrtf(var + LN_EPS);
        float aw = __ldg(attn_w + h) * TEMP_INV;
        float m = -3.4e38f;
#pragma unroll
        for (int c = 0; c < C; c++) {
            float n = fmaf((f[c] - mu) * rs, __ldg(ln_gamma + h * C + c),
                           __ldg(ln_beta + h * C + c));
            f[c] = n;
            m = fmaxf(m, n * aw);
        }
        float s = 0.f;
#pragma unroll
        for (int c = 0; c < C; c++) { e[c] = expf(f[c] * aw - m); s += e[c]; }
        float inv = 1.0f / s;
        ull hid2[16];
#pragma unroll
        for (int d = 0; d < 16; d++) hid2[d] = 0ull;
#pragma unroll
        for (int c = 0; c < C; c++) {
            float a = f[c] * e[c] * inv;
            ull a2 = pack2(a, a);
            const ull* wr = reinterpret_cast<const ull*>(Wh + (h * C + c) * C);
#pragma unroll
            for (int d = 0; d < 16; d++) ffma2(hid2[d], a2, wr[d]);
        }
#pragma unroll
        for (int d = 0; d < 16; d++) {
            float2 hv = unpack2(hid2[d]);
            __nv_bfloat162 hv2(__float2bfloat16(mishf(hv.x)),
                               __float2bfloat16(mishf(hv.y)));
            uint32_t off = tx * XSTR + (h * 32 + 2 * d) * 2;
            *(uint32_t*)(smc + OFF_XHI + off) = *reinterpret_cast<uint32_t*>(&hv2);
        }
    }
    __syncthreads();

    // ---- GEMM1: H1 = mish(X @ Wah) -----------------------------------------
    mma_gemm(gWahHi, 32, xh_lane, acc, wid, tx);
    __syncthreads();   // all X reads done -> overwrite with H1
#pragma unroll
    for (int mi = 0; mi < 2; mi++)
#pragma unroll
        for (int nb = 0; nb < 4; nb++)
#pragma unroll
            for (int rb = 0; rb < 2; rb++) {
                int row = mi * 16 + rb * 8 + gq;
                int n = wn0 + nb * 8 + 2 * tg;
                __nv_bfloat162 hv2(__float2bfloat16(mishf(acc[mi][nb][rb * 2])),
                                   __float2bfloat16(mishf(acc[mi][nb][rb * 2 + 1])));
                *(uint32_t*)(smc + OFF_XHI + row * XSTR + n * 2) =
                    *reinterpret_cast<uint32_t*>(&hv2);
            }
    __syncthreads();

    // ---- GEMM2: logits = H1 @ Waa ------------------------------------------
    mma_gemm(gWaaHi, 32, xh_lane, acc, wid, tx);

    // ---- epilogue -----------------------------------------------------------
    float mx[4] = {-3.4e38f, -3.4e38f, -3.4e38f, -3.4e38f};
#pragma unroll
    for (int mi = 0; mi < 2; mi++)
#pragma unroll
        for (int nb = 0; nb < 4; nb++)
#pragma unroll
            for (int rb = 0; rb < 2; rb++)
                mx[mi * 2 + rb] = fmaxf(mx[mi * 2 + rb],
                    fmaxf(acc[mi][nb][rb * 2], acc[mi][nb][rb * 2 + 1]));
#pragma unroll
    for (int q = 0; q < 4; q++) {
        mx[q] = fmaxf(mx[q], __shfl_xor_sync(FULL, mx[q], 1));
        mx[q] = fmaxf(mx[q], __shfl_xor_sync(FULL, mx[q], 2));
    }
    if (tg == 0) {
#pragma unroll
        for (int q = 0; q < 4; q++)
            ps0[wid * 32 + (q >> 1) * 16 + (q & 1) * 8 + gq] = mx[q];
    }
    __syncthreads();
    if (tid < 32) {
        float m = -3.4e38f;
#pragma unroll
        for (int w = 0; w < 16; w++) m = fmaxf(m, ps0[w * 32 + tid]);
        gmaxA[tid] = m;
    }
    __syncthreads();

    float sv[4] = {0.f, 0.f, 0.f, 0.f}, dv[4] = {0.f, 0.f, 0.f, 0.f};
#pragma unroll
    for (int mi = 0; mi < 2; mi++)
#pragma unroll
        for (int rb = 0; rb < 2; rb++) {
            int row = mi * 16 + rb * 8 + gq;
            float gm = gmaxA[row];
            float s = 0.f, d = 0.f;
#pragma unroll
            for (int nb = 0; nb < 4; nb++) {
                int n = wn0 + nb * 8 + 2 * tg;
                float e0 = expf((acc[mi][nb][rb * 2]     - gm) * TEMP_INV);
                float e1 = expf((acc[mi][nb][rb * 2 + 1] - gm) * TEMP_INV);
                float2 hh = unbf2(*(const uint32_t*)(smc + OFF_XHI + row * XSTR + n * 2));
                float2 bb = __half22float2(bh2[mi][nb][rb]);
                float2 wo = *(const float2*)(sWo + n);
                s += e0 + e1;
                d = fmaf(e0 * hh.x * bb.x, wo.x, d);
                d = fmaf(e1 * hh.y * bb.y, wo.y, d);
            }
            sv[mi * 2 + rb] = s; dv[mi * 2 + rb] = d;
        }
#pragma unroll
    for (int q = 0; q < 4; q++) {
        sv[q] += __shfl_xor_sync(FULL, sv[q], 1);
        sv[q] += __shfl_xor_sync(FULL, sv[q], 2);
        dv[q] += __shfl_xor_sync(FULL, dv[q], 1);
        dv[q] += __shfl_xor_sync(FULL, dv[q], 2);
    }
    if (tg == 0) {
#pragma unroll
        for (int q = 0; q < 4; q++) {
            int row = (q >> 1) * 16 + (q & 1) * 8 + gq;
            ps0[wid * 32 + row] = sv[q];
            ps1[wid * 32 + row] = dv[q];
        }
    }
    __syncthreads();
    if (tid < 32) {
        float S = 0.f, D = 0.f;
#pragma unroll
        for (int w = 0; w < 16; w++) { S += ps0[w * 32 + tid]; D += ps1[w * 32 + tid]; }
        float alpha = 0.f;
        const float4* sk4 = (const float4*)(sku + (size_t)(b0 + tid) * SKUD);
#pragma unroll
        for (int q = 0; q < 16; q++) {
            float4 s4 = sk4[q];
            alpha += s4.x * sWaWo[4 * q]     + s4.y * sWaWo[4 * q + 1]
                   + s4.z * sWaWo[4 * q + 2] + s4.w * sWaWo[4 * q + 3];
        }
        out[b0 + tid] = D / S + alpha;
    }
}

extern "C" void kernel_launch(void* const* d_in, const int* in_sizes, int n_in,
                              void* d_out, int out_size)
{
    const float* inputs   = (const float*)d_in[0];
    const float* sku      = (const float*)d_in[1];
    const float* deltas   = (const float*)d_in[2];
    const float* ln_gamma = (const float*)d_in[3];
    const float* ln_beta  = (const float*)d_in[4];
    const float* attn_w   = (const float*)d_in[5];
    const float* Wh       = (const float*)d_in[6];
    const float* Wah      = (const float*)d_in[7];
    const float* Waa      = (const float*)d_in[8];
    const float* Wb       = (const float*)d_in[9];
    const float* Wa       = (const float*)d_in[10];
    const float* Wo       = (const float*)d_in[11];
    float* out = (float*)d_out;

    int B = in_sizes[0] / H;
    prep_kernel<<<1088, 256>>>(Wah, Waa, Wb);
    cudaFuncSetAttribute(holiday_mma_kernel,
                         cudaFuncAttributeMaxDynamicSharedMemorySize, SMEM_BYTES);
    holiday_mma_kernel<<<B / ROWS, NTHR, SMEM_BYTES>>>(
        inputs, sku, deltas, ln_gamma, ln_beta, attn_w, Wh, Wa, Wo, out);
}

// round 17
// speedup vs baseline: 3.8613x; 1.5228x over previous
#include <cuda_runtime.h>
#include <cuda_fp16.h>
#include <cuda_bf16.h>
#include <math.h>
#include <stdint.h>

// prep-built bf16 weight images, LDG.128-friendly frag order:
// u32 idx = ((kb*16 + warp)*32 + lane)*8 + nbi*2 + reg   (nbi = nb within warp)
__device__ __align__(16) uint32_t gWahHi[131072];
__device__ __align__(16) uint32_t gWaaHi[131072];
__device__ __align__(16) uint32_t gWbHi [16384];
// Wh frag image: idx = h*512 + lane*16 + (kb*4+nb)*2 + reg
__device__ __align__(16) uint32_t gWhF  [8192];

namespace {
constexpr int H = 16, C = 32, HID = 512, SKUD = 64, ROWS = 32, NTHR = 512;
constexpr float TEMP_INV = 1.0f / 0.7f, TMAX = 365.0f, LN_EPS = 1e-3f;
constexpr int XSTR = 1040;                 // X image row stride in bytes (520 bf16)
// smem byte offsets
constexpr int OFF_XHI = 0;                 // 32*1040 = 33280
constexpr int OFF_WO  = 33280;             // 512 f32
constexpr int OFF_PS0 = 35328;             // 16*32 f32
constexpr int OFF_PS1 = 37376;             // 16*32 f32
constexpr int OFF_GMX = 39424;             // 32 f32
constexpr int OFF_WAWO= 39552;             // 64 f32
constexpr int SMEM_BYTES = 39808;
}

__device__ __forceinline__ float mish_fast(float x) {
    float sp = (x > 15.f) ? x : __logf(1.f + __expf(x));
    float t; asm("tanh.approx.f32 %0, %1;" : "=f"(t) : "f"(sp));
    return x * t;
}
__device__ __forceinline__ uint32_t s2u(const void* p) {
    uint32_t a;
    asm("{ .reg .u64 t; cvta.to.shared.u64 t, %1; cvt.u32.u64 %0, t; }" : "=r"(a) : "l"(p));
    return a;
}
__device__ __forceinline__ float2 unbf2(uint32_t u) {
    __nv_bfloat162 v = *reinterpret_cast<__nv_bfloat162*>(&u);
    return make_float2(__bfloat162float(v.x), __bfloat162float(v.y));
}
__device__ __forceinline__ uint32_t bf2pack(float a, float b) {
    __nv_bfloat162 v(__float2bfloat16(a), __float2bfloat16(b));
    return *reinterpret_cast<uint32_t*>(&v);
}
__device__ __forceinline__ void hmma(float* acc, uint32_t a0, uint32_t a1,
                                     uint32_t a2, uint32_t a3, uint32_t b0, uint32_t b1) {
    asm("mma.sync.aligned.m16n8k16.row.col.f32.bf16.bf16.f32 "
        "{%0,%1,%2,%3}, {%4,%5,%6,%7}, {%8,%9}, {%0,%1,%2,%3};"
        : "+f"(acc[0]), "+f"(acc[1]), "+f"(acc[2]), "+f"(acc[3])
        : "r"(a0), "r"(a1), "r"(a2), "r"(a3), "r"(b0), "r"(b1));
}
__device__ __forceinline__ void ldsm4(uint32_t* r, uint32_t addr) {
    asm volatile("ldmatrix.sync.aligned.m8n8.x4.shared.b16 {%0,%1,%2,%3}, [%4];"
        : "=r"(r[0]), "=r"(r[1]), "=r"(r[2]), "=r"(r[3]) : "r"(addr));
}

// single-pass bf16 MMA GEMM, barrier-free. Warp tile 32 rows x 32 cols.
__device__ __forceinline__ void mma_gemm(
    const uint32_t* __restrict__ gHi, int nk,
    uint32_t xh_lane, float acc[2][4][4], int wid, int tx)
{
#pragma unroll
    for (int mi = 0; mi < 2; mi++)
#pragma unroll
        for (int nb = 0; nb < 4; nb++)
#pragma unroll
            for (int e = 0; e < 4; e++) acc[mi][nb][e] = 0.f;

    const uint4* pH = (const uint4*)gHi;
    const int bidx = (wid * 32 + tx) * 2;   // uint4 index; +1024 per kb

    uint4 bh[2][2];
    bh[0][0] = __ldg(pH + bidx);     bh[0][1] = __ldg(pH + bidx + 1);
#pragma unroll 2
    for (int kb = 0; kb < nk; kb++) {
        int cur = kb & 1, nxt = cur ^ 1;
        if (kb + 1 < nk) {
            int p = bidx + (kb + 1) * 1024;
            bh[nxt][0] = __ldg(pH + p);     bh[nxt][1] = __ldg(pH + p + 1);
        }
        uint32_t ah[2][4];
#pragma unroll
        for (int mi = 0; mi < 2; mi++)
            ldsm4(ah[mi], xh_lane + mi * 16 * XSTR + kb * 32);
        uint32_t bhr[8];
        bhr[0] = bh[cur][0].x; bhr[1] = bh[cur][0].y; bhr[2] = bh[cur][0].z; bhr[3] = bh[cur][0].w;
        bhr[4] = bh[cur][1].x; bhr[5] = bh[cur][1].y; bhr[6] = bh[cur][1].z; bhr[7] = bh[cur][1].w;
#pragma unroll
        for (int nb = 0; nb < 4; nb++)
#pragma unroll
            for (int mi = 0; mi < 2; mi++)
                hmma(acc[mi][nb], ah[mi][0], ah[mi][1], ah[mi][2], ah[mi][3],
                     bhr[2 * nb], bhr[2 * nb + 1]);
    }
}

// ---------- prep: build frag-order bf16 weight images ------------------------
__global__ void prep_kernel(const float* __restrict__ Wah,
                            const float* __restrict__ Waa,
                            const float* __restrict__ Wb,
                            const float* __restrict__ Wh)
{
    int gid = blockIdx.x * 256 + threadIdx.x;
    if (gid >= 286720) return;
    if (gid >= 278528) {
        // Wh frag image
        int idx = gid - 278528;
        int reg = idx & 1, q = (idx >> 1) & 7, lane = (idx >> 4) & 31, h = idx >> 9;
        int kb = q >> 2, nb = q & 3;
        int tg = lane & 3, gq = lane >> 2;
        int k0 = kb * 16 + 2 * tg + reg * 8;
        int n  = nb * 8 + gq;
        float w0 = Wh[(h * 32 + k0) * 32 + n];
        float w1 = Wh[(h * 32 + k0 + 1) * 32 + n];
        gWhF[idx] = bf2pack(w0, w1);
        return;
    }
    const float* W; uint32_t* dHi; int idx;
    if (gid < 131072)      { W = Wah; dHi = gWahHi; idx = gid; }
    else if (gid < 262144) { W = Waa; dHi = gWaaHi; idx = gid - 131072; }
    else                   { W = Wb;  dHi = gWbHi;  idx = gid - 262144; }
    int reg = idx & 1, lane = (idx >> 1) & 31, nb = (idx >> 6) & 63, kb = idx >> 12;
    int tg = lane & 3, gq = lane >> 2;
    int k0 = kb * 16 + 2 * tg + reg * 8;
    int n  = nb * 8 + gq;
    float w0 = W[(size_t)k0 * 512 + n];
    float w1 = W[(size_t)(k0 + 1) * 512 + n];
    int w = nb >> 2, nbi = nb & 3;
    uint32_t nidx = (uint32_t)(((kb * 16 + w) * 32 + lane) * 8 + nbi * 2 + reg);
    dHi[nidx] = bf2pack(w0, w1);
}

__global__ __launch_bounds__(NTHR)
void holiday_mma_kernel(
    const float* __restrict__ inputs, const float* __restrict__ sku,
    const float* __restrict__ deltas, const float* __restrict__ ln_gamma,
    const float* __restrict__ ln_beta, const float* __restrict__ attn_w,
    const float* __restrict__ Wa, const float* __restrict__ Wo,
    float* __restrict__ out)
{
    extern __shared__ char smc[];
    float* sWo   = (float*)(smc + OFF_WO);
    float* ps0   = (float*)(smc + OFF_PS0);
    float* ps1   = (float*)(smc + OFF_PS1);
    float* gmaxA = (float*)(smc + OFF_GMX);
    float* sWaWo = (float*)(smc + OFF_WAWO);

    const int tid = threadIdx.x, tx = tid & 31, wid = tid >> 5;   // 16 warps
    const int tg = tx & 3, gq = tx >> 2;
    const int wn0 = wid * 32;
    const int b0 = blockIdx.x * ROWS;
    const unsigned FULL = 0xffffffffu;
    const uint32_t sb = s2u(smc);
    const uint32_t lrow = (tx & 7) + ((tx >> 3) & 1) * 8;
    const uint32_t lcol = (tx >> 4) * 16;
    const uint32_t xh_lane = sb + OFF_XHI + lrow * XSTR + lcol;

    // ---- prologue: Wo, alpha fold, changepoints ----------------------------
    for (int i = tid; i < HID; i += NTHR) sWo[i] = Wo[i];
#pragma unroll
    for (int si = 0; si < 4; si++) {
        int s = wid * 4 + si;
        float p = 0.f;
#pragma unroll
        for (int j = 0; j < 16; j++) {
            int c = tx + 32 * j;
            p = fmaf(__ldg(Wa + s * HID + c), __ldg(Wo + c), p);
        }
#pragma unroll
        for (int o = 16; o > 0; o >>= 1) p += __shfl_xor_sync(FULL, p, o);
        if (tx == 0) sWaWo[s] = p;
    }
    float cps_r;
    {
        float d  = deltas[wid * C + tx];
        float sp = (d > 15.f) ? d : __logf(1.f + __expf(d));
        float s  = sp;
#pragma unroll
        for (int o = 1; o < 32; o <<= 1) {
            float v = __shfl_up_sync(FULL, s, o);
            if (tx >= o) s += v;
        }
        cps_r = s * (TMAX / __shfl_sync(FULL, s, 31));
    }

    // ---- stage sku into X image (rows 0..31, k 0..63) ----------------------
    {
        int r = tid >> 4, k0 = (tid & 15) * 4;
        float4 a = *(const float4*)(sku + (size_t)(b0 + r) * SKUD + k0);
        uint32_t off = r * XSTR + k0 * 2;
        *(uint32_t*)(smc + OFF_XHI + off)     = bf2pack(a.x, a.y);
        *(uint32_t*)(smc + OFF_XHI + off + 4) = bf2pack(a.z, a.w);
    }
    __syncthreads();

    float acc[2][4][4];

    // ---- GEMM0: beta = sigmoid(sku @ Wb) -> half2 regs ---------------------
    mma_gemm(gWbHi, 4, xh_lane, acc, wid, tx);
    __half2 bh2[2][4][2];
#pragma unroll
    for (int mi = 0; mi < 2; mi++)
#pragma unroll
        for (int nb = 0; nb < 4; nb++) {
            bh2[mi][nb][0] = __floats2half2_rn(
                1.f / (1.f + __expf(-acc[mi][nb][0])), 1.f / (1.f + __expf(-acc[mi][nb][1])));
            bh2[mi][nb][1] = __floats2half2_rn(
                1.f / (1.f + __expf(-acc[mi][nb][2])), 1.f / (1.f + __expf(-acc[mi][nb][3])));
        }
    __syncthreads();   // all GEMM0 sku reads done -> stage1 may overwrite X

    // ---- stage 1: features -> attended (bf16, warp-private) -> Wh MMA ------
    {
        const int h = wid;
        float t = inputs[(size_t)(b0 + tx) * H + h];
        float f[C];
        float mu = 0.f;
#pragma unroll
        for (int c = 0; c < C; c++) {
            float cp = __shfl_sync(FULL, cps_r, c);
            f[c] = fmaxf(t - cp, 0.f); mu += f[c];
        }
        mu *= (1.0f / C);
        float var = 0.f;
#pragma unroll
        for (int c = 0; c < C; c++) { float d = f[c] - mu; var = fmaf(d, d, var); }
        var *= (1.0f / C);
        float rs = rsqrtf(var + LN_EPS);
        float aw = __ldg(attn_w + h) * TEMP_INV;
        float m = -3.4e38f;
#pragma unroll
        for (int c = 0; c < C; c++) {
            float n = fmaf((f[c] - mu) * rs, __ldg(ln_gamma + h * C + c),
                           __ldg(ln_beta + h * C + c));
            f[c] = n;
            m = fmaxf(m, n * aw);
        }
        float s = 0.f;
#pragma unroll
        for (int c = 0; c < C; c++) s += __expf(f[c] * aw - m);
        float inv = 1.0f / s;

        // store attended (bf16) into this warp's X column block, row = tx
        uint32_t xatt = sb + OFF_XHI + tx * XSTR + h * 64;
#pragma unroll
        for (int j = 0; j < 4; j++) {
            uint32_t u[4];
#pragma unroll
            for (int e = 0; e < 4; e++) {
                int c = j * 8 + e * 2;
                float a0 = f[c]     * __expf(f[c]     * aw - m) * inv;
                float a1 = f[c + 1] * __expf(f[c + 1] * aw - m) * inv;
                u[e] = bf2pack(a0, a1);
            }
            asm volatile("st.shared.v4.b32 [%0], {%1,%2,%3,%4};"
                :: "r"(xatt + j * 16), "r"(u[0]), "r"(u[1]), "r"(u[2]), "r"(u[3])
                : "memory");
        }
        __syncwarp();

        // hid = attended @ Wh_h  via 16 HMMA (warp-private)
        uint32_t af[2][2][4];
#pragma unroll
        for (int mi = 0; mi < 2; mi++)
#pragma unroll
            for (int kb = 0; kb < 2; kb++)
                ldsm4(af[mi][kb], xh_lane + h * 64 + mi * 16 * XSTR + kb * 32);
        const uint4* pw = (const uint4*)gWhF + h * 128 + tx * 4;
        uint4 w0 = __ldg(pw), w1 = __ldg(pw + 1), w2 = __ldg(pw + 2), w3 = __ldg(pw + 3);
        uint32_t whf[16] = {w0.x, w0.y, w0.z, w0.w, w1.x, w1.y, w1.z, w1.w,
                            w2.x, w2.y, w2.z, w2.w, w3.x, w3.y, w3.z, w3.w};
        float hc[2][4][4];
#pragma unroll
        for (int mi = 0; mi < 2; mi++)
#pragma unroll
            for (int nb = 0; nb < 4; nb++)
#pragma unroll
                for (int e = 0; e < 4; e++) hc[mi][nb][e] = 0.f;
#pragma unroll
        for (int kb = 0; kb < 2; kb++)
#pragma unroll
            for (int nb = 0; nb < 4; nb++) {
                uint32_t b0f = whf[(kb * 4 + nb) * 2];
                uint32_t b1f = whf[(kb * 4 + nb) * 2 + 1];
#pragma unroll
                for (int mi = 0; mi < 2; mi++)
                    hmma(hc[mi][nb], af[mi][kb][0], af[mi][kb][1],
                         af[mi][kb][2], af[mi][kb][3], b0f, b1f);
            }
        // mish -> X image (same warp-private column block)
#pragma unroll
        for (int mi = 0; mi < 2; mi++)
#pragma unroll
            for (int nb = 0; nb < 4; nb++)
#pragma unroll
                for (int rb = 0; rb < 2; rb++) {
                    int row = mi * 16 + rb * 8 + gq;
                    int col = h * 32 + nb * 8 + 2 * tg;
                    *(uint32_t*)(smc + OFF_XHI + row * XSTR + col * 2) =
                        bf2pack(mish_fast(hc[mi][nb][rb * 2]),
                                mish_fast(hc[mi][nb][rb * 2 + 1]));
                }
    }
    __syncthreads();

    // ---- GEMM1: H1 = mish(X @ Wah) -----------------------------------------
    mma_gemm(gWahHi, 32, xh_lane, acc, wid, tx);
    __syncthreads();   // all X reads done -> overwrite with H1
#pragma unroll
    for (int mi = 0; mi < 2; mi++)
#pragma unroll
        for (int nb = 0; nb < 4; nb++)
#pragma unroll
            for (int rb = 0; rb < 2; rb++) {
                int row = mi * 16 + rb * 8 + gq;
                int n = wn0 + nb * 8 + 2 * tg;
                *(uint32_t*)(smc + OFF_XHI + row * XSTR + n * 2) =
                    bf2pack(mish_fast(acc[mi][nb][rb * 2]),
                            mish_fast(acc[mi][nb][rb * 2 + 1]));
            }
    __syncthreads();

    // ---- GEMM2: logits = H1 @ Waa ------------------------------------------
    mma_gemm(gWaaHi, 32, xh_lane, acc, wid, tx);

    // ---- epilogue -----------------------------------------------------------
    float mx[4] = {-3.4e38f, -3.4e38f, -3.4e38f, -3.4e38f};
#pragma unroll
    for (int mi = 0; mi < 2; mi++)
#pragma unroll
        for (int nb = 0; nb < 4; nb++)
#pragma unroll
            for (int rb = 0; rb < 2; rb++)
                mx[mi * 2 + rb] = fmaxf(mx[mi * 2 + rb],
                    fmaxf(acc[mi][nb][rb * 2], acc[mi][nb][rb * 2 + 1]));
#pragma unroll
    for (int q = 0; q < 4; q++) {
        mx[q] = fmaxf(mx[q], __shfl_xor_sync(FULL, mx[q], 1));
        mx[q] = fmaxf(mx[q], __shfl_xor_sync(FULL, mx[q], 2));
    }
    if (tg == 0) {
#pragma unroll
        for (int q = 0; q < 4; q++)
            ps0[wid * 32 + (q >> 1) * 16 + (q & 1) * 8 + gq] = mx[q];
    }
    __syncthreads();
    if (tid < 32) {
        float m = -3.4e38f;
#pragma unroll
        for (int w = 0; w < 16; w++) m = fmaxf(m, ps0[w * 32 + tid]);
        gmaxA[tid] = m;
    }
    __syncthreads();

    float sv[4] = {0.f, 0.f, 0.f, 0.f}, dv[4] = {0.f, 0.f, 0.f, 0.f};
#pragma unroll
    for (int mi = 0; mi < 2; mi++)
#pragma unroll
        for (int rb = 0; rb < 2; rb++) {
            int row = mi * 16 + rb * 8 + gq;
            float gm = gmaxA[row];
            float s = 0.f, d = 0.f;
#pragma unroll
            for (int nb = 0; nb < 4; nb++) {
                int n = wn0 + nb * 8 + 2 * tg;
                float e0 = __expf((acc[mi][nb][rb * 2]     - gm) * TEMP_INV);
                float e1 = __expf((acc[mi][nb][rb * 2 + 1] - gm) * TEMP_INV);
                float2 hh = unbf2(*(const uint32_t*)(smc + OFF_XHI + row * XSTR + n * 2));
                float2 bb = __half22float2(bh2[mi][nb][rb]);
                float2 wo = *(const float2*)(sWo + n);
                s += e0 + e1;
                d = fmaf(e0 * hh.x * bb.x, wo.x, d);
                d = fmaf(e1 * hh.y * bb.y, wo.y, d);
            }
            sv[mi * 2 + rb] = s; dv[mi * 2 + rb] = d;
        }
#pragma unroll
    for (int q = 0; q < 4; q++) {
        sv[q] += __shfl_xor_sync(FULL, sv[q], 1);
        sv[q] += __shfl_xor_sync(FULL, sv[q], 2);
        dv[q] += __shfl_xor_sync(FULL, dv[q], 1);
        dv[q] += __shfl_xor_sync(FULL, dv[q], 2);
    }
    if (tg == 0) {
#pragma unroll
        for (int q = 0; q < 4; q++) {
            int row = (q >> 1) * 16 + (q & 1) * 8 + gq;
            ps0[wid * 32 + row] = sv[q];
            ps1[wid * 32 + row] = dv[q];
        }
    }
    __syncthreads();
    if (tid < 32) {
        float S = 0.f, D = 0.f;
#pragma unroll
        for (int w = 0; w < 16; w++) { S += ps0[w * 32 + tid]; D += ps1[w * 32 + tid]; }
        float alpha = 0.f;
        const float4* sk4 = (const float4*)(sku + (size_t)(b0 + tid) * SKUD);
#pragma unroll
        for (int q = 0; q < 16; q++) {
            float4 s4 = sk4[q];
            alpha += s4.x * sWaWo[4 * q]     + s4.y * sWaWo[4 * q + 1]
                   + s4.z * sWaWo[4 * q + 2] + s4.w * sWaWo[4 * q + 3];
        }
        out[b0 + tid] = D / S + alpha;
    }
}

extern "C" void kernel_launch(void* const* d_in, const int* in_sizes, int n_in,
                              void* d_out, int out_size)
{
    const float* inputs   = (const float*)d_in[0];
    const float* sku      = (const float*)d_in[1];
    const float* deltas   = (const float*)d_in[2];
    const float* ln_gamma = (const float*)d_in[3];
    const float* ln_beta  = (const float*)d_in[4];
    const float* attn_w   = (const float*)d_in[5];
    const float* Wh       = (const float*)d_in[6];
    const float* Wah      = (const float*)d_in[7];
    const float* Waa      = (const float*)d_in[8];
    const float* Wb       = (const float*)d_in[9];
    const float* Wa       = (const float*)d_in[10];
    const float* Wo       = (const float*)d_in[11];
    float* out = (float*)d_out;

    int B = in_sizes[0] / H;
    prep_kernel<<<1120, 256>>>(Wah, Waa, Wb, Wh);
    cudaFuncSetAttribute(holiday_mma_kernel,
                         cudaFuncAttributeMaxDynamicSharedMemorySize, SMEM_BYTES);
    holiday_mma_kernel<<<B / ROWS, NTHR, SMEM_BYTES>>>(
        inputs, sku, deltas, ln_gamma, ln_beta, attn_w, Wa, Wo, out);
}